// round 7
// baseline (speedup 1.0000x reference)
#include <cuda_runtime.h>
#include <cuda_bf16.h>
#include <cstdint>

#define NUM_CLASSES 100000
#define EMBED 512
#define BATCH_N 4096
#define LAMBDA_C 0.01f
#define ALPHA_C 0.1f

#define NCS ((size_t)NUM_CLASSES * EMBED)   // 51,200,000 floats
#define N4  (NCS / 4)                        // 12,800,000 float4s

// Pure streaming copy centers -> new_centers (= out+1, 4B misaligned):
// aligned LDG.128, 4x scalar STG.32. Two independent float4s per thread.
// Block 0 thread 0 also zeroes the loss slot.
__global__ __launch_bounds__(256)
void copy_kernel(const float4* __restrict__ src,
                 float* __restrict__ dst,
                 float* __restrict__ loss) {
    const size_t base = (size_t)blockIdx.x * 512 + threadIdx.x;
    if (base == 0) *loss = 0.0f;

    float4 a = __ldcs(src + base);
    float4 b = __ldcs(src + base + 256);

    float* da = dst + base * 4;
    __stcs(da + 0, a.x);
    __stcs(da + 1, a.y);
    __stcs(da + 2, a.z);
    __stcs(da + 3, a.w);

    float* db = dst + (base + 256) * 4;
    __stcs(db + 0, b.x);
    __stcs(db + 1, b.y);
    __stcs(db + 2, b.z);
    __stcs(db + 3, b.w);
}

// Fixup: one block per sample. y (16KB) staged in smem; each block scans for
// duplicate-class samples. Every block adds its own loss term; the
// minimum-index block per class ("leader") overwrites the touched row.
__global__ __launch_bounds__(128)
void fixup_kernel(const int* __restrict__ y,
                  const float4* __restrict__ batch4,
                  const float4* __restrict__ centers4,
                  float* __restrict__ dst,
                  float* __restrict__ loss) {
    __shared__ int s_y[BATCH_N];
    __shared__ int s_list[BATCH_N];   // safe upper bound on duplicates
    __shared__ int s_cnt;
    __shared__ float wsum[4];

    const int i = blockIdx.x;
    const int t = threadIdx.x;        // 0..127

    if (t == 0) s_cnt = 0;

    // stage y: 4096 ints = 1024 int4, 8 per thread
    const int4* y4 = reinterpret_cast<const int4*>(y);
    #pragma unroll
    for (int k = 0; k < 8; k++)
        reinterpret_cast<int4*>(s_y)[t + k * 128] = y4[t + k * 128];
    __syncthreads();

    const int c = s_y[i];

    // collect all samples of this class
    for (int k = t; k < BATCH_N; k += 128) {
        if (s_y[k] == c) {
            int p = atomicAdd(&s_cnt, 1);
            s_list[p] = k;
        }
    }
    __syncthreads();
    const int cnt = s_cnt;

    int leader = s_list[0];
    for (int k = 1; k < cnt; k++) leader = min(leader, s_list[k]);

    // own loss term (every block, duplicates included)
    float4 c4 = centers4[(size_t)c * (EMBED / 4) + t];
    {
        float4 b4 = batch4[(size_t)i * (EMBED / 4) + t];
        float dx = b4.x - c4.x, dy = b4.y - c4.y;
        float dz = b4.z - c4.z, dw = b4.w - c4.w;
        float ls = dx * dx + dy * dy + dz * dz + dw * dw;
        #pragma unroll
        for (int off = 16; off > 0; off >>= 1)
            ls += __shfl_xor_sync(0xFFFFFFFFu, ls, off);
        if ((t & 31) == 0) wsum[t >> 5] = ls;
        __syncthreads();
        if (t == 0) {
            float tot = wsum[0] + wsum[1] + wsum[2] + wsum[3];
            atomicAdd(loss, tot * (LAMBDA_C / (float)BATCH_N));
        }
    }

    // leader overwrites the touched row (single writer per class)
    if (i == leader) {
        float ax = 0.f, ay = 0.f, az = 0.f, aw = 0.f;
        for (int m = 0; m < cnt; m++) {
            int s = s_list[m];
            float4 b4 = batch4[(size_t)s * (EMBED / 4) + t];
            ax += b4.x - c4.x;
            ay += b4.y - c4.y;
            az += b4.z - c4.z;
            aw += b4.w - c4.w;
        }
        float* d = dst + (size_t)c * EMBED + t * 4;   // misaligned dst: scalars
        d[0] = c4.x + ALPHA_C * ax;
        d[1] = c4.y + ALPHA_C * ay;
        d[2] = c4.z + ALPHA_C * az;
        d[3] = c4.w + ALPHA_C * aw;
    }
}

extern "C" void kernel_launch(void* const* d_in, const int* in_sizes, int n_in,
                              void* d_out, int out_size) {
    const int*   y       = (const int*)d_in[0];
    const float* batch   = (const float*)d_in[1];
    const float* centers = (const float*)d_in[2];

    float* out = (float*)d_out;

    float* loss_ptr;
    float* new_centers;
    if (out_size == (int)(NCS + 1)) {
        loss_ptr = out;
        new_centers = out + 1;
    } else {
        new_centers = out;
        loss_ptr = out + NCS;
    }

    // 1) bulk copy (also zeroes loss). 12.8M float4s / 512 per block = 25000.
    copy_kernel<<<(unsigned)(N4 / 512), 256>>>(
        reinterpret_cast<const float4*>(centers), new_centers, loss_ptr);

    // 2) sparse fixup + loss
    fixup_kernel<<<BATCH_N, 128>>>(y,
        reinterpret_cast<const float4*>(batch),
        reinterpret_cast<const float4*>(centers),
        new_centers, loss_ptr);
}

// round 8
// speedup vs baseline: 1.0466x; 1.0466x over previous
#include <cuda_runtime.h>
#include <cuda_bf16.h>
#include <cstdint>

#define NUM_CLASSES 100000
#define EMBED 512
#define BATCH_N 4096
#define LAMBDA_C 0.01f
#define ALPHA_C 0.1f

#define NCS ((size_t)NUM_CLASSES * EMBED)   // 51,200,000 floats
#define N4  (NCS / 4)                        // 12,800,000 float4s

// Per-class chains. ZERO-INITIALIZED at module load; fixup restores zeros
// after use, so the all-zero invariant holds on every call (no memset pass).
// Encoding: g_head[c] == 0 -> empty; == i+1 -> sample i is chain head.
__device__ int g_head[NUM_CLASSES];
__device__ int g_next[BATCH_N];             // stores (prev sample + 1) or 0

// 1) build chains + zero loss slot
__global__ __launch_bounds__(256)
void build_kernel(const int* __restrict__ y, float* __restrict__ loss) {
    int i = blockIdx.x * blockDim.x + threadIdx.x;
    if (i == 0) *loss = 0.0f;
    if (i < BATCH_N) {
        int c = y[i];
        int old = atomicExch(&g_head[c], i + 1);
        g_next[i] = old;
    }
}

// 2) pure streaming copy centers -> new_centers (= out+1, 4B misaligned):
//    aligned LDG.128, 4x scalar STG.32. One float4 per thread (R2-proven).
__global__ __launch_bounds__(256)
void copy_kernel(const float4* __restrict__ src, float* __restrict__ dst) {
    const size_t i = (size_t)blockIdx.x * blockDim.x + threadIdx.x;
    float4 v = __ldcs(src + i);
    float* d = dst + i * 4;
    __stcs(d + 0, v.x);
    __stcs(d + 1, v.y);
    __stcs(d + 2, v.z);
    __stcs(d + 3, v.w);
}

// 3) fixup: one block per sample. Every block adds its own loss term.
//    The chain-head block overwrites the touched row and clears g_head[c].
__global__ __launch_bounds__(128)
void fixup_kernel(const int* __restrict__ y,
                  const float4* __restrict__ batch4,
                  const float4* __restrict__ centers4,
                  float* __restrict__ dst,
                  float* __restrict__ loss) {
    const int i = blockIdx.x;
    const int t = threadIdx.x;          // 0..127, one float4 each
    const int c = y[i];

    float4 c4 = centers4[(size_t)c * (EMBED / 4) + t];
    float4 b4 = batch4[(size_t)i * (EMBED / 4) + t];

    // own loss term (duplicates each contribute)
    {
        float dx = b4.x - c4.x, dy = b4.y - c4.y;
        float dz = b4.z - c4.z, dw = b4.w - c4.w;
        float ls = dx * dx + dy * dy + dz * dz + dw * dw;
        #pragma unroll
        for (int off = 16; off > 0; off >>= 1)
            ls += __shfl_xor_sync(0xFFFFFFFFu, ls, off);
        __shared__ float wsum[4];
        if ((t & 31) == 0) wsum[t >> 5] = ls;
        __syncthreads();
        if (t == 0) {
            float tot = wsum[0] + wsum[1] + wsum[2] + wsum[3];
            atomicAdd(loss, tot * (LAMBDA_C / (float)BATCH_N));
        }
    }

    // chain head: accumulate over all samples of this class, overwrite row,
    // then restore g_head[c] = 0 (keeps the zero-invariant for next call)
    if (g_head[c] == i + 1) {
        float ax = b4.x - c4.x;
        float ay = b4.y - c4.y;
        float az = b4.z - c4.z;
        float aw = b4.w - c4.w;
        int s = g_next[i];              // (next sample + 1) or 0
        while (s > 0) {
            float4 q4 = batch4[(size_t)(s - 1) * (EMBED / 4) + t];
            ax += q4.x - c4.x;
            ay += q4.y - c4.y;
            az += q4.z - c4.z;
            aw += q4.w - c4.w;
            s = g_next[s - 1];
        }
        float* d = dst + (size_t)c * EMBED + t * 4;   // misaligned dst: scalars
        d[0] = c4.x + ALPHA_C * ax;
        d[1] = c4.y + ALPHA_C * ay;
        d[2] = c4.z + ALPHA_C * az;
        d[3] = c4.w + ALPHA_C * aw;

        if (t == 0) g_head[c] = 0;
    }
}

extern "C" void kernel_launch(void* const* d_in, const int* in_sizes, int n_in,
                              void* d_out, int out_size) {
    const int*   y       = (const int*)d_in[0];
    const float* batch   = (const float*)d_in[1];
    const float* centers = (const float*)d_in[2];

    float* out = (float*)d_out;

    float* loss_ptr;
    float* new_centers;
    if (out_size == (int)(NCS + 1)) {
        loss_ptr = out;
        new_centers = out + 1;
    } else {
        new_centers = out;
        loss_ptr = out + NCS;
    }

    // 1) chains + loss zero (g_head is all-zero by invariant)
    build_kernel<<<(BATCH_N + 255) / 256, 256>>>(y, loss_ptr);

    // 2) bulk copy at full HBM rate (12.8M float4s, 1 per thread)
    copy_kernel<<<(unsigned)(N4 / 256), 256>>>(
        reinterpret_cast<const float4*>(centers), new_centers);

    // 3) sparse fixup of touched rows + loss; restores g_head zeros
    fixup_kernel<<<BATCH_N, 128>>>(y,
        reinterpret_cast<const float4*>(batch),
        reinterpret_cast<const float4*>(centers),
        new_centers, loss_ptr);
}

// round 9
// speedup vs baseline: 1.1424x; 1.0915x over previous
#include <cuda_runtime.h>
#include <cuda_bf16.h>
#include <cstdint>

#define NUM_CLASSES 100000
#define EMBED 512
#define BATCH_N 4096
#define LAMBDA_C 0.01f
#define ALPHA_C 0.1f

// Per-class chains. Zero-initialized at module load; the fused kernel
// restores zeros after use, so the invariant holds across calls/replays.
// Encoding: g_head[c] == 0 -> untouched; == i+1 -> sample i is chain head.
__device__ int g_head[NUM_CLASSES];
__device__ int g_next[BATCH_N];

// 1) build chains + zero loss slot
__global__ __launch_bounds__(256)
void build_kernel(const int* __restrict__ y, float* __restrict__ loss) {
    int i = blockIdx.x * blockDim.x + threadIdx.x;
    if (i == 0) *loss = 0.0f;
    if (i < BATCH_N) {
        int c = y[i];
        int old = atomicExch(&g_head[c], i + 1);
        g_next[i] = old;
    }
}

__device__ __forceinline__ void st_cs(float* p, float v) {
    asm volatile("st.global.cs.f32 [%0], %1;" :: "l"(p), "f"(v) : "memory");
}

// 2) fused streaming pass. Hot path is EXACTLY the pure copy (LDG.128 +
//    4x STG.32 via asm volatile — cannot be merged/eliminated); the rare
//    touched-row overwrite runs after, program-ordered on the same thread.
__global__ __launch_bounds__(256)
void fused_copy_apply_kernel(const float4* __restrict__ centers4,
                             const float4* __restrict__ batch4,
                             float* __restrict__ dst,
                             float* __restrict__ loss) {
    const int row = blockIdx.x * 2 + (threadIdx.x >> 7);
    const int t   = threadIdx.x & 127;          // float4 index within row

    const int h = g_head[row];                  // independent broadcast load
    float4 c4 = __ldcs(centers4 + (size_t)row * (EMBED / 4) + t);

    // unconditional copy store: depends only on c4 (pure-copy dependency)
    float* d = dst + (size_t)row * EMBED + t * 4;   // dst misaligned by 4B
    st_cs(d + 0, c4.x);
    st_cs(d + 1, c4.y);
    st_cs(d + 2, c4.z);
    st_cs(d + 3, c4.w);

    // rare path: row touched by >=1 sample -> overwrite with updated values
    if (h > 0) {
        float ax = 0.f, ay = 0.f, az = 0.f, aw = 0.f, ls0 = 0.f;
        // first sample in chain (h-1); also compute its loss term? No:
        // loss needs EVERY sample's term; walk adds all of them.
        int s = h;
        while (s > 0) {
            float4 b4 = batch4[(size_t)(s - 1) * (EMBED / 4) + t];
            float dx = b4.x - c4.x;
            float dy = b4.y - c4.y;
            float dz = b4.z - c4.z;
            float dw = b4.w - c4.w;
            ax += dx; ay += dy; az += dz; aw += dw;
            ls0 += dx * dx + dy * dy + dz * dz + dw * dw;
            s = g_next[s - 1];
        }
        // overwrite (same thread, same addresses -> ordered after st_cs)
        d[0] = c4.x + ALPHA_C * ax;
        d[1] = c4.y + ALPHA_C * ay;
        d[2] = c4.z + ALPHA_C * az;
        d[3] = c4.w + ALPHA_C * aw;

        // loss reduce: branch is row-uniform -> warp-uniform
        #pragma unroll
        for (int off = 16; off > 0; off >>= 1)
            ls0 += __shfl_xor_sync(0xFFFFFFFFu, ls0, off);
        if ((t & 31) == 0)
            atomicAdd(loss, ls0 * (LAMBDA_C / (float)BATCH_N));

        // restore zero-invariant for next call
        if (t == 0) g_head[row] = 0;
    }
}

extern "C" void kernel_launch(void* const* d_in, const int* in_sizes, int n_in,
                              void* d_out, int out_size) {
    const int*   y       = (const int*)d_in[0];
    const float* batch   = (const float*)d_in[1];
    const float* centers = (const float*)d_in[2];

    float* out = (float*)d_out;
    const size_t ncs = (size_t)NUM_CLASSES * EMBED;

    float* loss_ptr;
    float* new_centers;
    if (out_size == (int)(ncs + 1)) {
        loss_ptr = out;
        new_centers = out + 1;
    } else {
        new_centers = out;
        loss_ptr = out + ncs;
    }

    // 1) chains + loss zero (g_head all-zero by maintained invariant)
    build_kernel<<<(BATCH_N + 255) / 256, 256>>>(y, loss_ptr);

    // 2) fused streaming copy + sparse overwrite (+ g_head restore)
    fused_copy_apply_kernel<<<NUM_CLASSES / 2, 256>>>(
        reinterpret_cast<const float4*>(centers),
        reinterpret_cast<const float4*>(batch),
        new_centers, loss_ptr);
}